// round 13
// baseline (speedup 1.0000x reference)
#include <cuda_runtime.h>
#include <cuda_fp16.h>
#include <math.h>
#include <stdint.h>

#define NTOK 4096        // BATCH*SEQ
#define DM   1024
#define DFF  4096
#define SEQL 2048
#define HEADS 16
#define NQT  16          // SEQL / 128 q-tiles

// ---------------- scratch (no allocations allowed) ----------------
__device__ __half g_h16   [NTOK * DM];
__device__ __half g_qkv16 [NTOK * 3 * DM];
__device__ __half g_ctx16 [NTOK * DM];
__device__ float  g_first [NTOK * DM];
__device__ __half g_ff116 [NTOK * DFF];
__device__ __half g_wqkvh [3 * DM * DM];
__device__ __half g_woh   [DM * DM];
__device__ __half g_w1h   [DFF * DM];
__device__ __half g_w2h   [DM * DFF];

// =================== helpers ===================
__device__ __forceinline__ uint32_t smem_u32(const void* p) {
    uint32_t a;
    asm("{ .reg .u64 t; cvta.to.shared.u64 t, %1; cvt.u32.u64 %0, t; }" : "=r"(a) : "l"(p));
    return a;
}
#define CP_ASYNC16(dst, src) asm volatile("cp.async.cg.shared.global [%0], [%1], 16;" :: "r"(dst), "l"(src))
#define CP_COMMIT() asm volatile("cp.async.commit_group;" ::: "memory")
#define CP_WAIT(n)  asm volatile("cp.async.wait_group %0;" :: "n"(n) : "memory")

#define LDSM4(r, a) asm volatile("ldmatrix.sync.aligned.m8n8.x4.shared.b16 {%0,%1,%2,%3}, [%4];" \
    : "=r"((r)[0]), "=r"((r)[1]), "=r"((r)[2]), "=r"((r)[3]) : "r"(a))
#define LDSM4T(r, a) asm volatile("ldmatrix.sync.aligned.m8n8.x4.trans.shared.b16 {%0,%1,%2,%3}, [%4];" \
    : "=r"((r)[0]), "=r"((r)[1]), "=r"((r)[2]), "=r"((r)[3]) : "r"(a))

#define MMA16816(d, a, b) asm volatile( \
    "mma.sync.aligned.m16n8k16.row.col.f32.f16.f16.f32 " \
    "{%0,%1,%2,%3},{%4,%5,%6,%7},{%8,%9},{%0,%1,%2,%3};" \
    : "+f"((d)[0]), "+f"((d)[1]), "+f"((d)[2]), "+f"((d)[3]) \
    : "r"((a)[0]), "r"((a)[1]), "r"((a)[2]), "r"((a)[3]), "r"((b)[0]), "r"((b)[1]))

// single-instruction fp32x2 -> fp16x2 pack (lo = a, hi = b)
__device__ __forceinline__ uint32_t pack2(float a, float b) {
    uint32_t r;
    asm("cvt.rn.f16x2.f32 %0, %1, %2;" : "=r"(r) : "f"(b), "f"(a));
    return r;
}
// p = exp2fp16(pack(a,b)); accumulates fp32 sum of the two fp16 results
__device__ __forceinline__ uint32_t exp2pack(float a, float b, float& sum) {
    uint32_t s = pack2(a, b);
    __half2 p = h2exp2(*(__half2*)&s);
    float2 f = __half22float2(p);
    sum += f.x + f.y;
    return *(uint32_t*)&p;
}
__device__ __forceinline__ float gelu_erf(float x) {
    return 0.5f * x * (1.0f + erff(x * 0.70710678118654752f));
}

#define SCALE_LOG2E 0.1803368801111601f   // 0.125 * log2(e)
#define V_SCALE 0.0625f                   // 2^-4: shift folded into V
#define INV_V_SCALE 16.0f

// ---------------- fused weight convert: all 4 weights fp32 -> fp16 ----------------
__global__ void __launch_bounds__(256) convert_all(
    const float4* __restrict__ wqkv, const float4* __restrict__ wo,
    const float4* __restrict__ w1,   const float4* __restrict__ w2,
    __half* __restrict__ dq, __half* __restrict__ do_,
    __half* __restrict__ d1, __half* __restrict__ d2)
{
    size_t i = (size_t)blockIdx.x * 256 + threadIdx.x;
    const float4* src;
    __half* dst;
    size_t off;
    if (i < 786432)        { src = wqkv; dst = dq;  off = i; }
    else if (i < 1048576)  { src = wo;   dst = do_; off = i - 786432; }
    else if (i < 2097152)  { src = w1;   dst = d1;  off = i - 1048576; }
    else                   { src = w2;   dst = d2;  off = i - 2097152; }
    float4 v = src[off];
    *(uint2*)(dst + off * 4) = make_uint2(pack2(v.x, v.y), pack2(v.z, v.w));
}

// ---------------- RMSNorm -> fp16 output ----------------
__global__ void __launch_bounds__(256) rmsnorm_cv(
    const float* __restrict__ x, const float* __restrict__ w, __half* __restrict__ out)
{
    int row = blockIdx.x;
    int t = threadIdx.x;
    float4 v = ((const float4*)(x + (size_t)row * DM))[t];
    float ss = v.x * v.x + v.y * v.y + v.z * v.z + v.w * v.w;
    #pragma unroll
    for (int m = 16; m > 0; m >>= 1) ss += __shfl_xor_sync(0xffffffffu, ss, m);
    __shared__ float red[8];
    __shared__ float s_inv;
    if ((t & 31) == 0) red[t >> 5] = ss;
    __syncthreads();
    if (t == 0) {
        float tot = 0.f;
        #pragma unroll
        for (int i = 0; i < 8; i++) tot += red[i];
        s_inv = 1.0f / sqrtf(tot / (float)DM + 1e-5f);
    }
    __syncthreads();
    float inv = s_inv;
    float4 wv = ((const float4*)w)[t];
    v.x *= inv * wv.x; v.y *= inv * wv.y; v.z *= inv * wv.z; v.w *= inv * wv.w;
    *(uint2*)(out + (size_t)row * DM + t * 4) = make_uint2(pack2(v.x, v.y), pack2(v.z, v.w));
}

// =================== persistent fp16 mma.sync GEMM, 256x128 tiles ===================
// C[M,N] = A[M,K] * B[N,K]^T (+epilogue). 512 threads (16 warps: 4x4 grid,
// m64 x n32 per warp). K-chunk 64, 3 stages x 48KB (A 32KB + B 16KB), grid 148.
// Halves L2->SMEM traffic per FLOP vs 128x128.
// EPI: 0 = plain fp32, 1 = erf-GELU -> fp16, 2 = residual fp32,
//      3 = fp16 QKV epilogue: Q cols (<DM) * SCALE_LOG2E, V cols (>=2*DM) * 2^-4
#define GSTAGE 49152
#define GEMM_SMEM (3 * GSTAGE)
#define GEMM_GRID 148

template<int EPI>
__global__ void __launch_bounds__(512, 1) gemm_mma(
    const __half* __restrict__ A, const __half* __restrict__ B,
    const float* __restrict__ R, float* __restrict__ C, __half* __restrict__ Ccv,
    int M, int N, int K)
{
    extern __shared__ char smem[];
    const uint32_t sb = smem_u32(smem);
    const int tid = threadIdx.x;
    const int w = tid >> 5, l = tid & 31;
    const int warp_m = w & 3, warp_n = w >> 2;      // 4 x 4 warp grid
    const int nbn = N >> 7;
    const int ntiles = (M >> 8) * nbn;              // 256-row M tiles
    const int stride = gridDim.x;
    const size_t rowB = (size_t)K * 2;
    const int nc = K >> 6;

    // loader: A rows rr+64i (i<4), B rows rr+64i (i<2); 8 chunks of 16B per 128B row
    const int rr = tid >> 3, cc = tid & 7;          // rr 0..63
    const uint32_t swo = ((cc ^ (rr & 7)) << 4);
    const uint32_t dAs = sb + rr * 128 + swo;           // A dest base (stage 0)
    const uint32_t dBs = sb + 32768 + rr * 128 + swo;   // B dest base (stage 0)
    const size_t rstep = rowB << 6;                 // 64 rows

    int tload = blockIdx.x;
    int cload = 0;
    int sload = 0;
    const char *pA = nullptr, *pB = nullptr;
    if (tload < ntiles) {
        int bm = (tload / nbn) << 8, bn = (tload % nbn) << 7;
        pA = (const char*)A + (size_t)(bm + rr) * rowB + cc * 16;
        pB = (const char*)B + (size_t)(bn + rr) * rowB + cc * 16;
    }

    #define ISSUE() do { \
        if (tload < ntiles) { \
            uint32_t _soff = (uint32_t)sload * GSTAGE; \
            size_t _g = (size_t)cload * 128; \
            _Pragma("unroll") \
            for (int i = 0; i < 4; i++) \
                CP_ASYNC16(dAs + _soff + i * 8192, pA + _g + i * rstep); \
            _Pragma("unroll") \
            for (int i = 0; i < 2; i++) \
                CP_ASYNC16(dBs + _soff + i * 8192, pB + _g + i * rstep); \
            if (++cload == nc) { \
                cload = 0; tload += stride; \
                if (tload < ntiles) { \
                    int _bm = (tload / nbn) << 8, _bn = (tload % nbn) << 7; \
                    pA = (const char*)A + (size_t)(_bm + rr) * rowB + cc * 16; \
                    pB = (const char*)B + (size_t)(_bn + rr) * rowB + cc * 16; \
                } \
            } \
        } \
        sload = (sload + 1 == 3) ? 0 : sload + 1; \
        CP_COMMIT(); \
    } while (0)

    ISSUE();
    ISSUE();

    const int ra = warp_m * 64 + (l & 15);                      // + mt*16
    const int ca_half = (l >> 4);
    const int rb = warp_n * 32 + ((l >> 4) & 1) * 8 + (l & 7);  // + p*16
    const int cb_half = (l >> 3) & 1;

    int scons = 0;
    for (int t = blockIdx.x; t < ntiles; t += stride) {
        const int bm = (t / nbn) << 8, bn = (t % nbn) << 7;

        float d[4][4][4];
        #pragma unroll
        for (int mt = 0; mt < 4; mt++)
            #pragma unroll
            for (int nt = 0; nt < 4; nt++)
                #pragma unroll
                for (int j = 0; j < 4; j++) d[mt][nt][j] = 0.f;

        for (int c = 0; c < nc; c++) {
            CP_WAIT(1);
            __syncthreads();
            ISSUE();

            const uint32_t sA = sb + (uint32_t)scons * GSTAGE;
            const uint32_t sB = sA + 32768;

            #pragma unroll
            for (int ks = 0; ks < 4; ks++) {
                uint32_t ah[4][4], bh[2][4];
                #pragma unroll
                for (int mt = 0; mt < 4; mt++) {
                    int r = ra + mt * 16;
                    int ch = 2 * ks + ca_half;
                    LDSM4(ah[mt], sA + r * 128 + (((ch ^ (r & 7))) << 4));
                }
                #pragma unroll
                for (int p = 0; p < 2; p++) {
                    int r = rb + p * 16;
                    int ch = 2 * ks + cb_half;
                    LDSM4(bh[p], sB + r * 128 + (((ch ^ (r & 7))) << 4));
                }
                #pragma unroll
                for (int mt = 0; mt < 4; mt++)
                    #pragma unroll
                    for (int p = 0; p < 2; p++) {
                        MMA16816(d[mt][2 * p],     ah[mt], bh[p]);
                        MMA16816(d[mt][2 * p + 1], ah[mt], bh[p] + 2);
                    }
            }
            scons = (scons + 1 == 3) ? 0 : scons + 1;
        }

        const int gid = l >> 2, tid2 = l & 3;
        #pragma unroll
        for (int mt = 0; mt < 4; mt++) {
            #pragma unroll
            for (int nt = 0; nt < 4; nt++) {
                int col = bn + warp_n * 32 + nt * 8 + tid2 * 2;
                #pragma unroll
                for (int half = 0; half < 2; half++) {
                    int row = bm + warp_m * 64 + mt * 16 + gid + half * 8;
                    float v0 = d[mt][nt][half * 2], v1 = d[mt][nt][half * 2 + 1];
                    if (EPI == 0) {
                        *(float2*)&C[(size_t)row * N + col] = make_float2(v0, v1);
                    } else if (EPI == 2) {
                        float2 r2 = *(const float2*)&R[(size_t)row * N + col];
                        *(float2*)&C[(size_t)row * N + col] = make_float2(v0 + r2.x, v1 + r2.y);
                    } else {
                        if (EPI == 1) { v0 = gelu_erf(v0); v1 = gelu_erf(v1); }
                        if (EPI == 3) {
                            if (col < DM)          { v0 *= SCALE_LOG2E; v1 *= SCALE_LOG2E; }
                            else if (col >= 2 * DM){ v0 *= V_SCALE;     v1 *= V_SCALE; }
                        }
                        *(uint32_t*)(Ccv + (size_t)row * N + col) = pack2(v0, v1);
                    }
                }
            }
        }
    }
    #undef ISSUE
}

// =================== balanced fp16 causal flash attention (paired k-tiles) ===================
// Grid (NQT/2, HEADS, 2); CTA bx does q-tiles {NQT-1-bx, bx}. 2 CTAs/SM.
// Q pre-scaled by 0.125*log2e; V pre-scaled by 2^-4 -> p = exp2(s) raw.
// K-tiles processed in PAIRS per sync: smem Q 16KB + 2 pair-buffers x 32KB = 80KB.
#define ATTN_SMEM 81920

__global__ void __launch_bounds__(256, 2) attn_mma(
    const __half* __restrict__ qkv16, __half* __restrict__ ctx16)
{
    extern __shared__ char smem[];
    const uint32_t sb = smem_u32(smem);
    const int tid = threadIdx.x;
    const int w = tid >> 5, l = tid & 31;
    const int bx = blockIdx.x;
    const int h = blockIdx.y, b = blockIdx.z;
    const int btok = b * SEQL;
    const int wq0 = w * 16;
    const char* qkvb = (const char*)qkv16;
    const int qoff = 128 * h;
    const int koff = 2048 + 128 * h;
    const int voff = 4096 + 128 * h;

    #define PAIRLOAD(p) do { \
        uint32_t _pb = sb + 16384 + (uint32_t)((p) & 1) * 32768; \
        _Pragma("unroll") \
        for (int i = 0; i < 8; i++) { \
            int idx = tid + i * 256; \
            int t_ = idx >> 10; \
            int rem = idx & 1023; \
            int mat = rem >> 9; \
            int row = (rem >> 3) & 63; \
            int cc = rem & 7; \
            const char* _src = qkvb + (size_t)(btok + ((p) * 2 + t_) * 64 + row) * 6144 \
                + (mat ? voff : koff) + cc * 16; \
            CP_ASYNC16(_pb + t_ * 16384 + mat * 8192 + row * 128 + ((cc ^ (row & 7)) << 4), _src); \
        } \
    } while (0)

    #pragma unroll 1
    for (int pass = 0; pass < 2; pass++) {
        const int qt = pass ? bx : (NQT - 1 - bx);   // heavy first
        const int qbase = qt * 128;
        const int npairs = qt + 1;

        #pragma unroll
        for (int i = 0; i < 4; i++) {
            int idx = tid + i * 256;
            int row = idx >> 3, cc = idx & 7;
            const char* src = qkvb + (size_t)(btok + qbase + row) * 6144 + qoff + cc * 16;
            CP_ASYNC16(sb + row * 128 + ((cc ^ (row & 7)) << 4), src);
        }
        PAIRLOAD(0);
        CP_COMMIT();
        if (1 < npairs) PAIRLOAD(1);
        CP_COMMIT();

        CP_WAIT(1);
        __syncthreads();

        uint32_t qh[4][4];
        #pragma unroll
        for (int c = 0; c < 4; c++) {
            int cch = 2 * c + (l >> 4);
            int row = wq0 + (l & 15);
            LDSM4(qh[c], sb + row * 128 + ((cch ^ (row & 7)) << 4));
        }

        float o[8][4];
        #pragma unroll
        for (int nt = 0; nt < 8; nt++)
            #pragma unroll
            for (int j = 0; j < 4; j++) o[nt][j] = 0.f;
        float l0 = 0.f, l1 = 0.f;
        const int qrow0 = qbase + wq0 + (l >> 2);

        for (int p = 0; p < npairs; p++) {
            if (p) { CP_WAIT(1); __syncthreads(); }
            const uint32_t pb = sb + 16384 + (uint32_t)(p & 1) * 32768;

            #pragma unroll
            for (int tt = 0; tt < 2; tt++) {
                const int kt = 2 * p + tt;
                const int kbase = kt * 64;
                if (kbase > qbase + wq0 + 15) break;
                const uint32_t sK = pb + tt * 16384;
                const uint32_t sV = sK + 8192;

                float s4[8][4];
                #pragma unroll
                for (int nt = 0; nt < 8; nt++)
                    #pragma unroll
                    for (int j = 0; j < 4; j++) s4[nt][j] = 0.f;
                #pragma unroll
                for (int c = 0; c < 4; c++) {
                    int ch = 2 * c + ((l >> 3) & 1);
                    int rk = ((l >> 4) & 1) * 8 + (l & 7);
                    #pragma unroll
                    for (int nt2 = 0; nt2 < 4; nt2++) {
                        int r = nt2 * 16 + rk;
                        uint32_t bh[4];
                        LDSM4(bh, sK + r * 128 + ((ch ^ (r & 7)) << 4));
                        MMA16816(s4[2 * nt2],     qh[c], bh);
                        MMA16816(s4[2 * nt2 + 1], qh[c], bh + 2);
                    }
                }

                if (kbase + 63 > qbase + wq0) {
                    int col0 = kbase + 2 * (l & 3);
                    #pragma unroll
                    for (int nt = 0; nt < 8; nt++)
                        #pragma unroll
                        for (int j = 0; j < 4; j++) {
                            int col = col0 + nt * 8 + (j & 1);
                            int row = (j < 2) ? qrow0 : qrow0 + 8;
                            if (col > row) s4[nt][j] = -1e30f;
                        }
                }

                uint32_t pp[8][2];
                #pragma unroll
                for (int nt = 0; nt < 8; nt++) {
                    pp[nt][0] = exp2pack(s4[nt][0], s4[nt][1], l0);
                    pp[nt][1] = exp2pack(s4[nt][2], s4[nt][3], l1);
                }

                #pragma unroll
                for (int kc = 0; kc < 4; kc++) {
                    uint32_t aH[4];
                    aH[0] = pp[2 * kc][0];
                    aH[1] = pp[2 * kc][1];
                    aH[2] = pp[2 * kc + 1][0];
                    aH[3] = pp[2 * kc + 1][1];
                    int vrow = kc * 16 + ((l >> 3) & 1) * 8 + (l & 7);
                    #pragma unroll
                    for (int nt2 = 0; nt2 < 4; nt2++) {
                        int n = 2 * nt2 + (l >> 4);
                        uint32_t vh[4];
                        LDSM4T(vh, sV + vrow * 128 + ((n ^ (vrow & 7)) << 4));
                        MMA16816(o[2 * nt2],     aH, vh);
                        MMA16816(o[2 * nt2 + 1], aH, vh + 2);
                    }
                }
            }
            __syncthreads();
            if (p + 2 < npairs) PAIRLOAD(p + 2);
            CP_COMMIT();
        }

        #pragma unroll
        for (int msk = 1; msk < 4; msk <<= 1) {
            l0 += __shfl_xor_sync(0xffffffffu, l0, msk);
            l1 += __shfl_xor_sync(0xffffffffu, l1, msk);
        }
        float inv0 = INV_V_SCALE / l0, inv1 = INV_V_SCALE / l1;
        #pragma unroll
        for (int nt = 0; nt < 8; nt++) {
            int dh0 = nt * 8 + 2 * (l & 3);
            size_t base0 = (size_t)(btok + qrow0) * DM + h * 64 + dh0;
            *(uint32_t*)(ctx16 + base0) = pack2(o[nt][0] * inv0, o[nt][1] * inv0);
            size_t base1 = (size_t)(btok + qrow0 + 8) * DM + h * 64 + dh0;
            *(uint32_t*)(ctx16 + base1) = pack2(o[nt][2] * inv1, o[nt][3] * inv1);
        }
    }
    #undef PAIRLOAD
}

// ---------------- launch ----------------
extern "C" void kernel_launch(void* const* d_in, const int* in_sizes, int n_in,
                              void* d_out, int out_size)
{
    const float* x     = (const float*)d_in[0];
    const float* w_qkv = (const float*)d_in[1];
    const float* w_o   = (const float*)d_in[2];
    const float* ln1   = (const float*)d_in[3];
    const float* ln2   = (const float*)d_in[4];
    const float* w1    = (const float*)d_in[5];
    const float* w2    = (const float*)d_in[6];
    float* out = (float*)d_out;

    __half *h16, *qkv16, *ctx16, *ff116, *wqkvh, *woh, *w1h, *w2h;
    float *first;
    cudaGetSymbolAddress((void**)&h16, g_h16);
    cudaGetSymbolAddress((void**)&qkv16, g_qkv16);
    cudaGetSymbolAddress((void**)&ctx16, g_ctx16);
    cudaGetSymbolAddress((void**)&first, g_first);
    cudaGetSymbolAddress((void**)&ff116, g_ff116);
    cudaGetSymbolAddress((void**)&wqkvh, g_wqkvh);
    cudaGetSymbolAddress((void**)&woh, g_woh);
    cudaGetSymbolAddress((void**)&w1h, g_w1h);
    cudaGetSymbolAddress((void**)&w2h, g_w2h);

    cudaFuncSetAttribute(attn_mma, cudaFuncAttributeMaxDynamicSharedMemorySize, ATTN_SMEM);
    cudaFuncSetAttribute(gemm_mma<1>, cudaFuncAttributeMaxDynamicSharedMemorySize, GEMM_SMEM);
    cudaFuncSetAttribute(gemm_mma<2>, cudaFuncAttributeMaxDynamicSharedMemorySize, GEMM_SMEM);
    cudaFuncSetAttribute(gemm_mma<3>, cudaFuncAttributeMaxDynamicSharedMemorySize, GEMM_SMEM);

    // fused weight conversion
    convert_all<<<12288, 256>>>((const float4*)w_qkv, (const float4*)w_o,
                                (const float4*)w1, (const float4*)w2,
                                wqkvh, woh, w1h, w2h);

    // 1. h = rmsnorm(x, ln1) -> fp16
    rmsnorm_cv<<<NTOK, 256>>>(x, ln1, h16);
    // 2. qkv16 = fp16(h @ w_qkv^T), Q*0.125log2e, V*2^-4  (4096 x 3072 x 1024)
    gemm_mma<3><<<GEMM_GRID, 512, GEMM_SMEM>>>(h16, wqkvh, nullptr, nullptr, qkv16, NTOK, 3072, DM);
    // 3. ctx16 = causal_attention(qkv16)  — balanced pairs, paired k-tiles, 2 CTAs/SM
    attn_mma<<<dim3(NQT / 2, HEADS, 2), 256, ATTN_SMEM>>>(qkv16, ctx16);
    // 4. first = x + ctx @ w_o^T
    gemm_mma<2><<<GEMM_GRID, 512, GEMM_SMEM>>>(ctx16, woh, x, first, nullptr, NTOK, DM, DM);
    // 5. h = rmsnorm(first, ln2) -> fp16
    rmsnorm_cv<<<NTOK, 256>>>(first, ln2, h16);
    // 6. ff116 = fp16(gelu(h @ w1^T))
    gemm_mma<1><<<GEMM_GRID, 512, GEMM_SMEM>>>(h16, w1h, nullptr, nullptr, ff116, NTOK, DFF, DM);
    // 7. out = first + ff1 @ w2^T
    gemm_mma<2><<<GEMM_GRID, 512, GEMM_SMEM>>>(ff116, w2h, first, out, nullptr, NTOK, DM, DFF);
}

// round 14
// speedup vs baseline: 1.0509x; 1.0509x over previous
#include <cuda_runtime.h>
#include <cuda_fp16.h>
#include <math.h>
#include <stdint.h>

#define NTOK 4096        // BATCH*SEQ
#define DM   1024
#define DFF  4096
#define SEQL 2048
#define HEADS 16
#define NQT  16          // SEQL / 128 q-tiles

// ---------------- scratch (no allocations allowed) ----------------
__device__ __half g_h16   [NTOK * DM];
__device__ __half g_qkv16 [NTOK * 3 * DM];
__device__ __half g_ctx16 [NTOK * DM];
__device__ float  g_first [NTOK * DM];
__device__ __half g_ff116 [NTOK * DFF];
__device__ __half g_wqkvh [3 * DM * DM];
__device__ __half g_woh   [DM * DM];
__device__ __half g_w1h   [DFF * DM];
__device__ __half g_w2h   [DM * DFF];

// =================== helpers ===================
__device__ __forceinline__ uint32_t smem_u32(const void* p) {
    uint32_t a;
    asm("{ .reg .u64 t; cvta.to.shared.u64 t, %1; cvt.u32.u64 %0, t; }" : "=r"(a) : "l"(p));
    return a;
}
#define CP_ASYNC16(dst, src) asm volatile("cp.async.cg.shared.global [%0], [%1], 16;" :: "r"(dst), "l"(src))
#define CP_COMMIT() asm volatile("cp.async.commit_group;" ::: "memory")
#define CP_WAIT(n)  asm volatile("cp.async.wait_group %0;" :: "n"(n) : "memory")

#define LDSM4(r, a) asm volatile("ldmatrix.sync.aligned.m8n8.x4.shared.b16 {%0,%1,%2,%3}, [%4];" \
    : "=r"((r)[0]), "=r"((r)[1]), "=r"((r)[2]), "=r"((r)[3]) : "r"(a))
#define LDSM4T(r, a) asm volatile("ldmatrix.sync.aligned.m8n8.x4.trans.shared.b16 {%0,%1,%2,%3}, [%4];" \
    : "=r"((r)[0]), "=r"((r)[1]), "=r"((r)[2]), "=r"((r)[3]) : "r"(a))

#define MMA16816(d, a, b) asm volatile( \
    "mma.sync.aligned.m16n8k16.row.col.f32.f16.f16.f32 " \
    "{%0,%1,%2,%3},{%4,%5,%6,%7},{%8,%9},{%0,%1,%2,%3};" \
    : "+f"((d)[0]), "+f"((d)[1]), "+f"((d)[2]), "+f"((d)[3]) \
    : "r"((a)[0]), "r"((a)[1]), "r"((a)[2]), "r"((a)[3]), "r"((b)[0]), "r"((b)[1]))

// single-instruction fp32x2 -> fp16x2 pack (lo = a, hi = b)
__device__ __forceinline__ uint32_t pack2(float a, float b) {
    uint32_t r;
    asm("cvt.rn.f16x2.f32 %0, %1, %2;" : "=r"(r) : "f"(b), "f"(a));
    return r;
}
// p = exp2fp16(pack(a,b)); accumulates fp32 sum of the two fp16 results
__device__ __forceinline__ uint32_t exp2pack(float a, float b, float& sum) {
    uint32_t s = pack2(a, b);
    __half2 p = h2exp2(*(__half2*)&s);
    float2 f = __half22float2(p);
    sum += f.x + f.y;
    return *(uint32_t*)&p;
}
__device__ __forceinline__ float gelu_erf(float x) {
    return 0.5f * x * (1.0f + erff(x * 0.70710678118654752f));
}

#define SCALE_LOG2E 0.1803368801111601f   // 0.125 * log2(e)
#define V_SCALE 0.0625f                   // 2^-4: shift folded into V
#define INV_V_SCALE 16.0f

// ---------------- fused weight convert, 4 float4 per thread (MLP=4) ----------------
// float4 counts: wqkv 786432 | wo 262144 | w1 1048576 | w2 1048576 (total 3145728)
// grid 3072 x 256: thread base i4 = gid*4, 4 consecutive float4s.
__global__ void __launch_bounds__(256) convert_all(
    const float4* __restrict__ wqkv, const float4* __restrict__ wo,
    const float4* __restrict__ w1,   const float4* __restrict__ w2,
    __half* __restrict__ dq, __half* __restrict__ do_,
    __half* __restrict__ d1, __half* __restrict__ d2)
{
    size_t i0 = ((size_t)blockIdx.x * 256 + threadIdx.x) * 4;
    const float4* src;
    __half* dst;
    size_t off;
    if (i0 < 786432)       { src = wqkv; dst = dq;  off = i0; }
    else if (i0 < 1048576) { src = wo;   dst = do_; off = i0 - 786432; }
    else if (i0 < 2097152) { src = w1;   dst = d1;  off = i0 - 1048576; }
    else                   { src = w2;   dst = d2;  off = i0 - 2097152; }
    float4 v0 = src[off], v1 = src[off + 1], v2 = src[off + 2], v3 = src[off + 3];
    uint4 o0 = make_uint4(pack2(v0.x, v0.y), pack2(v0.z, v0.w),
                          pack2(v1.x, v1.y), pack2(v1.z, v1.w));
    uint4 o1 = make_uint4(pack2(v2.x, v2.y), pack2(v2.z, v2.w),
                          pack2(v3.x, v3.y), pack2(v3.z, v3.w));
    *(uint4*)(dst + off * 4)     = o0;
    *(uint4*)(dst + off * 4 + 8) = o1;
}

// ---------------- RMSNorm -> fp16, 2 rows per block (row ILP) ----------------
__global__ void __launch_bounds__(256) rmsnorm_cv(
    const float* __restrict__ x, const float* __restrict__ w, __half* __restrict__ out)
{
    int row0 = blockIdx.x * 2;
    int t = threadIdx.x;
    // two independent row loads in flight
    float4 va = ((const float4*)(x + (size_t)row0 * DM))[t];
    float4 vb = ((const float4*)(x + (size_t)(row0 + 1) * DM))[t];
    float4 wv = ((const float4*)w)[t];
    float sa = va.x * va.x + va.y * va.y + va.z * va.z + va.w * va.w;
    float sq = vb.x * vb.x + vb.y * vb.y + vb.z * vb.z + vb.w * vb.w;
    #pragma unroll
    for (int m = 16; m > 0; m >>= 1) {
        sa += __shfl_xor_sync(0xffffffffu, sa, m);
        sq += __shfl_xor_sync(0xffffffffu, sq, m);
    }
    __shared__ float red[2][8];
    __shared__ float s_inv[2];
    if ((t & 31) == 0) { red[0][t >> 5] = sa; red[1][t >> 5] = sq; }
    __syncthreads();
    if (t < 2) {
        float tot = 0.f;
        #pragma unroll
        for (int i = 0; i < 8; i++) tot += red[t][i];
        s_inv[t] = 1.0f / sqrtf(tot / (float)DM + 1e-5f);
    }
    __syncthreads();
    float ia = s_inv[0], ib = s_inv[1];
    va.x *= ia * wv.x; va.y *= ia * wv.y; va.z *= ia * wv.z; va.w *= ia * wv.w;
    vb.x *= ib * wv.x; vb.y *= ib * wv.y; vb.z *= ib * wv.z; vb.w *= ib * wv.w;
    *(uint2*)(out + (size_t)row0 * DM + t * 4) = make_uint2(pack2(va.x, va.y), pack2(va.z, va.w));
    *(uint2*)(out + (size_t)(row0 + 1) * DM + t * 4) = make_uint2(pack2(vb.x, vb.y), pack2(vb.z, vb.w));
}

// =================== persistent fp16 mma.sync GEMM (R12 config) ===================
// 128x128 tiles, K-chunk 64, 3 stages x 32KB, 2 CTAs/SM, persistent grid 296.
// EPI: 0 = plain fp32, 1 = erf-GELU -> fp16, 2 = residual fp32,
//      3 = fp16 QKV epilogue: Q cols (<DM) * SCALE_LOG2E, V cols (>=2*DM) * 2^-4
#define GSTAGE 32768
#define GEMM_SMEM (3 * GSTAGE)
#define GEMM_GRID 296

template<int EPI>
__global__ void __launch_bounds__(256, 2) gemm_mma(
    const __half* __restrict__ A, const __half* __restrict__ B,
    const float* __restrict__ R, float* __restrict__ C, __half* __restrict__ Ccv,
    int M, int N, int K)
{
    extern __shared__ char smem[];
    const uint32_t sb = smem_u32(smem);
    const int tid = threadIdx.x;
    const int w = tid >> 5, l = tid & 31;
    const int warp_m = w & 1, warp_n = w >> 1;
    const int nbn = N >> 7;
    const int ntiles = (M >> 7) * nbn;
    const int stride = gridDim.x;
    const size_t rowB = (size_t)K * 2;
    const int nc = K >> 6;

    const int rr = tid >> 3, cc = tid & 7;
    const uint32_t dA = sb + rr * 128 + ((cc ^ (rr & 7)) << 4);
    const size_t rstep = rowB << 5;

    int tload = blockIdx.x;
    int cload = 0;
    int sload = 0;
    const char *pA = nullptr, *pB = nullptr;
    if (tload < ntiles) {
        int bm = (tload / nbn) << 7, bn = (tload % nbn) << 7;
        pA = (const char*)A + (size_t)(bm + rr) * rowB + cc * 16;
        pB = (const char*)B + (size_t)(bn + rr) * rowB + cc * 16;
    }

    #define ISSUE() do { \
        if (tload < ntiles) { \
            uint32_t _soff = (uint32_t)sload * GSTAGE; \
            size_t _g = (size_t)cload * 128; \
            _Pragma("unroll") \
            for (int i = 0; i < 4; i++) { \
                CP_ASYNC16(dA + _soff + i * 4096,         pA + _g + i * rstep); \
                CP_ASYNC16(dA + _soff + 16384 + i * 4096, pB + _g + i * rstep); \
            } \
            if (++cload == nc) { \
                cload = 0; tload += stride; \
                if (tload < ntiles) { \
                    int _bm = (tload / nbn) << 7, _bn = (tload % nbn) << 7; \
                    pA = (const char*)A + (size_t)(_bm + rr) * rowB + cc * 16; \
                    pB = (const char*)B + (size_t)(_bn + rr) * rowB + cc * 16; \
                } \
            } \
        } \
        sload = (sload + 1 == 3) ? 0 : sload + 1; \
        CP_COMMIT(); \
    } while (0)

    ISSUE();
    ISSUE();

    const int ra = warp_m * 64 + (l & 15);
    const int ca_half = (l >> 4);
    const int rb = warp_n * 32 + ((l >> 4) & 1) * 8 + (l & 7);
    const int cb_half = (l >> 3) & 1;

    int scons = 0;
    for (int t = blockIdx.x; t < ntiles; t += stride) {
        const int bm = (t / nbn) << 7, bn = (t % nbn) << 7;

        float d[4][4][4];
        #pragma unroll
        for (int mt = 0; mt < 4; mt++)
            #pragma unroll
            for (int nt = 0; nt < 4; nt++)
                #pragma unroll
                for (int j = 0; j < 4; j++) d[mt][nt][j] = 0.f;

        for (int c = 0; c < nc; c++) {
            CP_WAIT(1);
            __syncthreads();
            ISSUE();

            const uint32_t sA = sb + (uint32_t)scons * GSTAGE;
            const uint32_t sB = sA + 16384;

            #pragma unroll
            for (int ks = 0; ks < 4; ks++) {
                uint32_t ah[4][4], bh[2][4];
                #pragma unroll
                for (int mt = 0; mt < 4; mt++) {
                    int r = ra + mt * 16;
                    int ch = 2 * ks + ca_half;
                    LDSM4(ah[mt], sA + r * 128 + (((ch ^ (r & 7))) << 4));
                }
                #pragma unroll
                for (int p = 0; p < 2; p++) {
                    int r = rb + p * 16;
                    int ch = 2 * ks + cb_half;
                    LDSM4(bh[p], sB + r * 128 + (((ch ^ (r & 7))) << 4));
                }
                #pragma unroll
                for (int mt = 0; mt < 4; mt++)
                    #pragma unroll
                    for (int p = 0; p < 2; p++) {
                        MMA16816(d[mt][2 * p],     ah[mt], bh[p]);
                        MMA16816(d[mt][2 * p + 1], ah[mt], bh[p] + 2);
                    }
            }
            scons = (scons + 1 == 3) ? 0 : scons + 1;
        }

        const int gid = l >> 2, tid2 = l & 3;
        #pragma unroll
        for (int mt = 0; mt < 4; mt++) {
            #pragma unroll
            for (int nt = 0; nt < 4; nt++) {
                int col = bn + warp_n * 32 + nt * 8 + tid2 * 2;
                #pragma unroll
                for (int half = 0; half < 2; half++) {
                    int row = bm + warp_m * 64 + mt * 16 + gid + half * 8;
                    float v0 = d[mt][nt][half * 2], v1 = d[mt][nt][half * 2 + 1];
                    if (EPI == 0) {
                        *(float2*)&C[(size_t)row * N + col] = make_float2(v0, v1);
                    } else if (EPI == 2) {
                        float2 r2 = *(const float2*)&R[(size_t)row * N + col];
                        *(float2*)&C[(size_t)row * N + col] = make_float2(v0 + r2.x, v1 + r2.y);
                    } else {
                        if (EPI == 1) { v0 = gelu_erf(v0); v1 = gelu_erf(v1); }
                        if (EPI == 3) {
                            if (col < DM)          { v0 *= SCALE_LOG2E; v1 *= SCALE_LOG2E; }
                            else if (col >= 2 * DM){ v0 *= V_SCALE;     v1 *= V_SCALE; }
                        }
                        *(uint32_t*)(Ccv + (size_t)row * N + col) = pack2(v0, v1);
                    }
                }
            }
        }
    }
    #undef ISSUE
}

// =================== balanced fp16 causal flash attention (paired k-tiles) ===================
// Grid (NQT/2, HEADS, 2); CTA bx does q-tiles {NQT-1-bx, bx}. 2 CTAs/SM.
// Q pre-scaled by 0.125*log2e; V pre-scaled by 2^-4 -> p = exp2(s) raw.
// K-tiles processed in PAIRS per sync: smem Q 16KB + 2 pair-buffers x 32KB = 80KB.
#define ATTN_SMEM 81920

__global__ void __launch_bounds__(256, 2) attn_mma(
    const __half* __restrict__ qkv16, __half* __restrict__ ctx16)
{
    extern __shared__ char smem[];
    const uint32_t sb = smem_u32(smem);
    const int tid = threadIdx.x;
    const int w = tid >> 5, l = tid & 31;
    const int bx = blockIdx.x;
    const int h = blockIdx.y, b = blockIdx.z;
    const int btok = b * SEQL;
    const int wq0 = w * 16;
    const char* qkvb = (const char*)qkv16;
    const int qoff = 128 * h;
    const int koff = 2048 + 128 * h;
    const int voff = 4096 + 128 * h;

    #define PAIRLOAD(p) do { \
        uint32_t _pb = sb + 16384 + (uint32_t)((p) & 1) * 32768; \
        _Pragma("unroll") \
        for (int i = 0; i < 8; i++) { \
            int idx = tid + i * 256; \
            int t_ = idx >> 10; \
            int rem = idx & 1023; \
            int mat = rem >> 9; \
            int row = (rem >> 3) & 63; \
            int cc = rem & 7; \
            const char* _src = qkvb + (size_t)(btok + ((p) * 2 + t_) * 64 + row) * 6144 \
                + (mat ? voff : koff) + cc * 16; \
            CP_ASYNC16(_pb + t_ * 16384 + mat * 8192 + row * 128 + ((cc ^ (row & 7)) << 4), _src); \
        } \
    } while (0)

    #pragma unroll 1
    for (int pass = 0; pass < 2; pass++) {
        const int qt = pass ? bx : (NQT - 1 - bx);   // heavy first
        const int qbase = qt * 128;
        const int npairs = qt + 1;

        #pragma unroll
        for (int i = 0; i < 4; i++) {
            int idx = tid + i * 256;
            int row = idx >> 3, cc = idx & 7;
            const char* src = qkvb + (size_t)(btok + qbase + row) * 6144 + qoff + cc * 16;
            CP_ASYNC16(sb + row * 128 + ((cc ^ (row & 7)) << 4), src);
        }
        PAIRLOAD(0);
        CP_COMMIT();
        if (1 < npairs) PAIRLOAD(1);
        CP_COMMIT();

        CP_WAIT(1);
        __syncthreads();

        uint32_t qh[4][4];
        #pragma unroll
        for (int c = 0; c < 4; c++) {
            int cch = 2 * c + (l >> 4);
            int row = wq0 + (l & 15);
            LDSM4(qh[c], sb + row * 128 + ((cch ^ (row & 7)) << 4));
        }

        float o[8][4];
        #pragma unroll
        for (int nt = 0; nt < 8; nt++)
            #pragma unroll
            for (int j = 0; j < 4; j++) o[nt][j] = 0.f;
        float l0 = 0.f, l1 = 0.f;
        const int qrow0 = qbase + wq0 + (l >> 2);

        for (int p = 0; p < npairs; p++) {
            if (p) { CP_WAIT(1); __syncthreads(); }
            const uint32_t pb = sb + 16384 + (uint32_t)(p & 1) * 32768;

            #pragma unroll
            for (int tt = 0; tt < 2; tt++) {
                const int kt = 2 * p + tt;
                const int kbase = kt * 64;
                if (kbase > qbase + wq0 + 15) break;
                const uint32_t sK = pb + tt * 16384;
                const uint32_t sV = sK + 8192;

                float s4[8][4];
                #pragma unroll
                for (int nt = 0; nt < 8; nt++)
                    #pragma unroll
                    for (int j = 0; j < 4; j++) s4[nt][j] = 0.f;
                #pragma unroll
                for (int c = 0; c < 4; c++) {
                    int ch = 2 * c + ((l >> 3) & 1);
                    int rk = ((l >> 4) & 1) * 8 + (l & 7);
                    #pragma unroll
                    for (int nt2 = 0; nt2 < 4; nt2++) {
                        int r = nt2 * 16 + rk;
                        uint32_t bh[4];
                        LDSM4(bh, sK + r * 128 + ((ch ^ (r & 7)) << 4));
                        MMA16816(s4[2 * nt2],     qh[c], bh);
                        MMA16816(s4[2 * nt2 + 1], qh[c], bh + 2);
                    }
                }

                if (kbase + 63 > qbase + wq0) {
                    int col0 = kbase + 2 * (l & 3);
                    #pragma unroll
                    for (int nt = 0; nt < 8; nt++)
                        #pragma unroll
                        for (int j = 0; j < 4; j++) {
                            int col = col0 + nt * 8 + (j & 1);
                            int row = (j < 2) ? qrow0 : qrow0 + 8;
                            if (col > row) s4[nt][j] = -1e30f;
                        }
                }

                uint32_t pp[8][2];
                #pragma unroll
                for (int nt = 0; nt < 8; nt++) {
                    pp[nt][0] = exp2pack(s4[nt][0], s4[nt][1], l0);
                    pp[nt][1] = exp2pack(s4[nt][2], s4[nt][3], l1);
                }

                #pragma unroll
                for (int kc = 0; kc < 4; kc++) {
                    uint32_t aH[4];
                    aH[0] = pp[2 * kc][0];
                    aH[1] = pp[2 * kc][1];
                    aH[2] = pp[2 * kc + 1][0];
                    aH[3] = pp[2 * kc + 1][1];
                    int vrow = kc * 16 + ((l >> 3) & 1) * 8 + (l & 7);
                    #pragma unroll
                    for (int nt2 = 0; nt2 < 4; nt2++) {
                        int n = 2 * nt2 + (l >> 4);
                        uint32_t vh[4];
                        LDSM4T(vh, sV + vrow * 128 + ((n ^ (vrow & 7)) << 4));
                        MMA16816(o[2 * nt2],     aH, vh);
                        MMA16816(o[2 * nt2 + 1], aH, vh + 2);
                    }
                }
            }
            __syncthreads();
            if (p + 2 < npairs) PAIRLOAD(p + 2);
            CP_COMMIT();
        }

        #pragma unroll
        for (int msk = 1; msk < 4; msk <<= 1) {
            l0 += __shfl_xor_sync(0xffffffffu, l0, msk);
            l1 += __shfl_xor_sync(0xffffffffu, l1, msk);
        }
        float inv0 = INV_V_SCALE / l0, inv1 = INV_V_SCALE / l1;
        #pragma unroll
        for (int nt = 0; nt < 8; nt++) {
            int dh0 = nt * 8 + 2 * (l & 3);
            size_t base0 = (size_t)(btok + qrow0) * DM + h * 64 + dh0;
            *(uint32_t*)(ctx16 + base0) = pack2(o[nt][0] * inv0, o[nt][1] * inv0);
            size_t base1 = (size_t)(btok + qrow0 + 8) * DM + h * 64 + dh0;
            *(uint32_t*)(ctx16 + base1) = pack2(o[nt][2] * inv1, o[nt][3] * inv1);
        }
    }
    #undef PAIRLOAD
}

// ---------------- launch ----------------
extern "C" void kernel_launch(void* const* d_in, const int* in_sizes, int n_in,
                              void* d_out, int out_size)
{
    const float* x     = (const float*)d_in[0];
    const float* w_qkv = (const float*)d_in[1];
    const float* w_o   = (const float*)d_in[2];
    const float* ln1   = (const float*)d_in[3];
    const float* ln2   = (const float*)d_in[4];
    const float* w1    = (const float*)d_in[5];
    const float* w2    = (const float*)d_in[6];
    float* out = (float*)d_out;

    __half *h16, *qkv16, *ctx16, *ff116, *wqkvh, *woh, *w1h, *w2h;
    float *first;
    cudaGetSymbolAddress((void**)&h16, g_h16);
    cudaGetSymbolAddress((void**)&qkv16, g_qkv16);
    cudaGetSymbolAddress((void**)&ctx16, g_ctx16);
    cudaGetSymbolAddress((void**)&first, g_first);
    cudaGetSymbolAddress((void**)&ff116, g_ff116);
    cudaGetSymbolAddress((void**)&wqkvh, g_wqkvh);
    cudaGetSymbolAddress((void**)&woh, g_woh);
    cudaGetSymbolAddress((void**)&w1h, g_w1h);
    cudaGetSymbolAddress((void**)&w2h, g_w2h);

    cudaFuncSetAttribute(attn_mma, cudaFuncAttributeMaxDynamicSharedMemorySize, ATTN_SMEM);
    cudaFuncSetAttribute(gemm_mma<1>, cudaFuncAttributeMaxDynamicSharedMemorySize, GEMM_SMEM);
    cudaFuncSetAttribute(gemm_mma<2>, cudaFuncAttributeMaxDynamicSharedMemorySize, GEMM_SMEM);
    cudaFuncSetAttribute(gemm_mma<3>, cudaFuncAttributeMaxDynamicSharedMemorySize, GEMM_SMEM);

    // fused weight conversion (4 float4 / thread)
    convert_all<<<3072, 256>>>((const float4*)w_qkv, (const float4*)w_o,
                               (const float4*)w1, (const float4*)w2,
                               wqkvh, woh, w1h, w2h);

    // 1. h = rmsnorm(x, ln1) -> fp16  (2 rows per block)
    rmsnorm_cv<<<NTOK / 2, 256>>>(x, ln1, h16);
    // 2. qkv16 = fp16(h @ w_qkv^T), Q*0.125log2e, V*2^-4  (4096 x 3072 x 1024)
    gemm_mma<3><<<GEMM_GRID, 256, GEMM_SMEM>>>(h16, wqkvh, nullptr, nullptr, qkv16, NTOK, 3072, DM);
    // 3. ctx16 = causal_attention(qkv16)  — balanced pairs, paired k-tiles, 2 CTAs/SM
    attn_mma<<<dim3(NQT / 2, HEADS, 2), 256, ATTN_SMEM>>>(qkv16, ctx16);
    // 4. first = x + ctx @ w_o^T
    gemm_mma<2><<<GEMM_GRID, 256, GEMM_SMEM>>>(ctx16, woh, x, first, nullptr, NTOK, DM, DM);
    // 5. h = rmsnorm(first, ln2) -> fp16
    rmsnorm_cv<<<NTOK / 2, 256>>>(first, ln2, h16);
    // 6. ff116 = fp16(gelu(h @ w1^T))
    gemm_mma<1><<<GEMM_GRID, 256, GEMM_SMEM>>>(h16, w1h, nullptr, nullptr, ff116, NTOK, DFF, DM);
    // 7. out = first + ff1 @ w2^T
    gemm_mma<2><<<GEMM_GRID, 256, GEMM_SMEM>>>(ff116, w2h, first, out, nullptr, NTOK, DM, DFF);
}

// round 15
// speedup vs baseline: 1.0870x; 1.0344x over previous
#include <cuda_runtime.h>
#include <cuda_fp16.h>
#include <math.h>
#include <stdint.h>

#define NTOK 4096        // BATCH*SEQ
#define DM   1024
#define DFF  4096
#define SEQL 2048
#define HEADS 16
#define NQT  16          // SEQL / 128 q-tiles

// ---------------- scratch (no allocations allowed) ----------------
__device__ __half g_h16   [NTOK * DM];
__device__ __half g_qkv16 [NTOK * 3 * DM];
__device__ __half g_ctx16 [NTOK * DM];
__device__ float  g_first [NTOK * DM];
__device__ __half g_ff116 [NTOK * DFF];
__device__ __half g_wqkvh [3 * DM * DM];
__device__ __half g_woh   [DM * DM];
__device__ __half g_w1h   [DFF * DM];
__device__ __half g_w2h   [DM * DFF];

// =================== helpers ===================
__device__ __forceinline__ uint32_t smem_u32(const void* p) {
    uint32_t a;
    asm("{ .reg .u64 t; cvta.to.shared.u64 t, %1; cvt.u32.u64 %0, t; }" : "=r"(a) : "l"(p));
    return a;
}
#define CP_ASYNC16(dst, src) asm volatile("cp.async.cg.shared.global [%0], [%1], 16;" :: "r"(dst), "l"(src))
#define CP_COMMIT() asm volatile("cp.async.commit_group;" ::: "memory")
#define CP_WAIT(n)  asm volatile("cp.async.wait_group %0;" :: "n"(n) : "memory")

#define LDSM4(r, a) asm volatile("ldmatrix.sync.aligned.m8n8.x4.shared.b16 {%0,%1,%2,%3}, [%4];" \
    : "=r"((r)[0]), "=r"((r)[1]), "=r"((r)[2]), "=r"((r)[3]) : "r"(a))
#define LDSM4T(r, a) asm volatile("ldmatrix.sync.aligned.m8n8.x4.trans.shared.b16 {%0,%1,%2,%3}, [%4];" \
    : "=r"((r)[0]), "=r"((r)[1]), "=r"((r)[2]), "=r"((r)[3]) : "r"(a))

#define MMA16816(d, a, b) asm volatile( \
    "mma.sync.aligned.m16n8k16.row.col.f32.f16.f16.f32 " \
    "{%0,%1,%2,%3},{%4,%5,%6,%7},{%8,%9},{%0,%1,%2,%3};" \
    : "+f"((d)[0]), "+f"((d)[1]), "+f"((d)[2]), "+f"((d)[3]) \
    : "r"((a)[0]), "r"((a)[1]), "r"((a)[2]), "r"((a)[3]), "r"((b)[0]), "r"((b)[1]))

// single-instruction fp32x2 -> fp16x2 pack (lo = a, hi = b)
__device__ __forceinline__ uint32_t pack2(float a, float b) {
    uint32_t r;
    asm("cvt.rn.f16x2.f32 %0, %1, %2;" : "=r"(r) : "f"(b), "f"(a));
    return r;
}
// p = exp2fp16(pack(a,b)); accumulates fp32 sum of the two fp16 results
__device__ __forceinline__ uint32_t exp2pack(float a, float b, float& sum) {
    uint32_t s = pack2(a, b);
    __half2 p = h2exp2(*(__half2*)&s);
    float2 f = __half22float2(p);
    sum += f.x + f.y;
    return *(uint32_t*)&p;
}
__device__ __forceinline__ float gelu_erf(float x) {
    return 0.5f * x * (1.0f + erff(x * 0.70710678118654752f));
}

#define SCALE_LOG2E 0.1803368801111601f   // 0.125 * log2(e)
#define V_SCALE 0.0625f                   // 2^-4: shift folded into V
#define INV_V_SCALE 16.0f

// ---------------- fused weight convert, 4 float4 per thread (MLP=4) ----------------
__global__ void __launch_bounds__(256) convert_all(
    const float4* __restrict__ wqkv, const float4* __restrict__ wo,
    const float4* __restrict__ w1,   const float4* __restrict__ w2,
    __half* __restrict__ dq, __half* __restrict__ do_,
    __half* __restrict__ d1, __half* __restrict__ d2)
{
    size_t i0 = ((size_t)blockIdx.x * 256 + threadIdx.x) * 4;
    const float4* src;
    __half* dst;
    size_t off;
    if (i0 < 786432)       { src = wqkv; dst = dq;  off = i0; }
    else if (i0 < 1048576) { src = wo;   dst = do_; off = i0 - 786432; }
    else if (i0 < 2097152) { src = w1;   dst = d1;  off = i0 - 1048576; }
    else                   { src = w2;   dst = d2;  off = i0 - 2097152; }
    float4 v0 = src[off], v1 = src[off + 1], v2 = src[off + 2], v3 = src[off + 3];
    uint4 o0 = make_uint4(pack2(v0.x, v0.y), pack2(v0.z, v0.w),
                          pack2(v1.x, v1.y), pack2(v1.z, v1.w));
    uint4 o1 = make_uint4(pack2(v2.x, v2.y), pack2(v2.z, v2.w),
                          pack2(v3.x, v3.y), pack2(v3.z, v3.w));
    *(uint4*)(dst + off * 4)     = o0;
    *(uint4*)(dst + off * 4 + 8) = o1;
}

// ---------------- RMSNorm -> fp16, 2 rows per block (row ILP) ----------------
__global__ void __launch_bounds__(256) rmsnorm_cv(
    const float* __restrict__ x, const float* __restrict__ w, __half* __restrict__ out)
{
    int row0 = blockIdx.x * 2;
    int t = threadIdx.x;
    float4 va = ((const float4*)(x + (size_t)row0 * DM))[t];
    float4 vb = ((const float4*)(x + (size_t)(row0 + 1) * DM))[t];
    float4 wv = ((const float4*)w)[t];
    float sa = va.x * va.x + va.y * va.y + va.z * va.z + va.w * va.w;
    float sq = vb.x * vb.x + vb.y * vb.y + vb.z * vb.z + vb.w * vb.w;
    #pragma unroll
    for (int m = 16; m > 0; m >>= 1) {
        sa += __shfl_xor_sync(0xffffffffu, sa, m);
        sq += __shfl_xor_sync(0xffffffffu, sq, m);
    }
    __shared__ float red[2][8];
    __shared__ float s_inv[2];
    if ((t & 31) == 0) { red[0][t >> 5] = sa; red[1][t >> 5] = sq; }
    __syncthreads();
    if (t < 2) {
        float tot = 0.f;
        #pragma unroll
        for (int i = 0; i < 8; i++) tot += red[t][i];
        s_inv[t] = 1.0f / sqrtf(tot / (float)DM + 1e-5f);
    }
    __syncthreads();
    float ia = s_inv[0], ib = s_inv[1];
    va.x *= ia * wv.x; va.y *= ia * wv.y; va.z *= ia * wv.z; va.w *= ia * wv.w;
    vb.x *= ib * wv.x; vb.y *= ib * wv.y; vb.z *= ib * wv.z; vb.w *= ib * wv.w;
    *(uint2*)(out + (size_t)row0 * DM + t * 4) = make_uint2(pack2(va.x, va.y), pack2(va.z, va.w));
    *(uint2*)(out + (size_t)(row0 + 1) * DM + t * 4) = make_uint2(pack2(vb.x, vb.y), pack2(vb.z, vb.w));
}

// =================== persistent fp16 mma.sync GEMM, compile-time N/K ===================
// 128x128 tiles, K-chunk 64, 3 stages x 32KB, 2 CTAs/SM, persistent grid 296. M = NTOK.
// EPI: 0 = plain fp32, 1 = erf-GELU -> fp16, 2 = residual fp32,
//      3 = fp16 QKV epilogue: Q cols (<DM) * SCALE_LOG2E, V cols (>=2*DM) * 2^-4
#define GSTAGE 32768
#define GEMM_SMEM (3 * GSTAGE)
#define GEMM_GRID 296

template<int EPI, int N, int K>
__global__ void __launch_bounds__(256, 2) gemm_mma(
    const __half* __restrict__ A, const __half* __restrict__ B,
    const float* __restrict__ R, float* __restrict__ C, __half* __restrict__ Ccv)
{
    extern __shared__ char smem[];
    const uint32_t sb = smem_u32(smem);
    const int tid = threadIdx.x;
    const int w = tid >> 5, l = tid & 31;
    const int warp_m = w & 1, warp_n = w >> 1;
    constexpr int nbn = N >> 7;
    constexpr int ntiles = (NTOK >> 7) * nbn;
    constexpr size_t rowB = (size_t)K * 2;
    constexpr int nc = K >> 6;
    constexpr size_t rstep = rowB << 5;
    const int stride = gridDim.x;

    const int rr = tid >> 3, cc = tid & 7;
    const uint32_t dA = sb + rr * 128 + ((cc ^ (rr & 7)) << 4);

    int tload = blockIdx.x;
    int cload = 0;
    int sload = 0;
    const char *pA = nullptr, *pB = nullptr;
    if (tload < ntiles) {
        int bm = (tload / nbn) << 7, bn = (tload % nbn) << 7;
        pA = (const char*)A + (size_t)(bm + rr) * rowB + cc * 16;
        pB = (const char*)B + (size_t)(bn + rr) * rowB + cc * 16;
    }

    #define ISSUE() do { \
        if (tload < ntiles) { \
            uint32_t _soff = (uint32_t)sload * GSTAGE; \
            size_t _g = (size_t)cload * 128; \
            _Pragma("unroll") \
            for (int i = 0; i < 4; i++) { \
                CP_ASYNC16(dA + _soff + i * 4096,         pA + _g + i * rstep); \
                CP_ASYNC16(dA + _soff + 16384 + i * 4096, pB + _g + i * rstep); \
            } \
            if (++cload == nc) { \
                cload = 0; tload += stride; \
                if (tload < ntiles) { \
                    int _bm = (tload / nbn) << 7, _bn = (tload % nbn) << 7; \
                    pA = (const char*)A + (size_t)(_bm + rr) * rowB + cc * 16; \
                    pB = (const char*)B + (size_t)(_bn + rr) * rowB + cc * 16; \
                } \
            } \
        } \
        sload = (sload + 1 == 3) ? 0 : sload + 1; \
        CP_COMMIT(); \
    } while (0)

    ISSUE();
    ISSUE();

    const int ra = warp_m * 64 + (l & 15);
    const int ca_half = (l >> 4);
    const int rb = warp_n * 32 + ((l >> 4) & 1) * 8 + (l & 7);
    const int cb_half = (l >> 3) & 1;

    int scons = 0;
    for (int t = blockIdx.x; t < ntiles; t += stride) {
        const int bm = (t / nbn) << 7, bn = (t % nbn) << 7;

        float d[4][4][4];
        #pragma unroll
        for (int mt = 0; mt < 4; mt++)
            #pragma unroll
            for (int nt = 0; nt < 4; nt++)
                #pragma unroll
                for (int j = 0; j < 4; j++) d[mt][nt][j] = 0.f;

        for (int c = 0; c < nc; c++) {
            CP_WAIT(1);
            __syncthreads();
            ISSUE();

            const uint32_t sA = sb + (uint32_t)scons * GSTAGE;
            const uint32_t sB = sA + 16384;

            #pragma unroll
            for (int ks = 0; ks < 4; ks++) {
                uint32_t ah[4][4], bh[2][4];
                #pragma unroll
                for (int mt = 0; mt < 4; mt++) {
                    int r = ra + mt * 16;
                    int ch = 2 * ks + ca_half;
                    LDSM4(ah[mt], sA + r * 128 + (((ch ^ (r & 7))) << 4));
                }
                #pragma unroll
                for (int p = 0; p < 2; p++) {
                    int r = rb + p * 16;
                    int ch = 2 * ks + cb_half;
                    LDSM4(bh[p], sB + r * 128 + (((ch ^ (r & 7))) << 4));
                }
                #pragma unroll
                for (int mt = 0; mt < 4; mt++)
                    #pragma unroll
                    for (int p = 0; p < 2; p++) {
                        MMA16816(d[mt][2 * p],     ah[mt], bh[p]);
                        MMA16816(d[mt][2 * p + 1], ah[mt], bh[p] + 2);
                    }
            }
            scons = (scons + 1 == 3) ? 0 : scons + 1;
        }

        const int gid = l >> 2, tid2 = l & 3;
        #pragma unroll
        for (int mt = 0; mt < 4; mt++) {
            #pragma unroll
            for (int nt = 0; nt < 4; nt++) {
                int col = bn + warp_n * 32 + nt * 8 + tid2 * 2;
                #pragma unroll
                for (int half = 0; half < 2; half++) {
                    int row = bm + warp_m * 64 + mt * 16 + gid + half * 8;
                    float v0 = d[mt][nt][half * 2], v1 = d[mt][nt][half * 2 + 1];
                    if (EPI == 0) {
                        *(float2*)&C[(size_t)row * N + col] = make_float2(v0, v1);
                    } else if (EPI == 2) {
                        float2 r2 = *(const float2*)&R[(size_t)row * N + col];
                        *(float2*)&C[(size_t)row * N + col] = make_float2(v0 + r2.x, v1 + r2.y);
                    } else {
                        if (EPI == 1) { v0 = gelu_erf(v0); v1 = gelu_erf(v1); }
                        if (EPI == 3) {
                            if (col < DM)          { v0 *= SCALE_LOG2E; v1 *= SCALE_LOG2E; }
                            else if (col >= 2 * DM){ v0 *= V_SCALE;     v1 *= V_SCALE; }
                        }
                        *(uint32_t*)(Ccv + (size_t)row * N + col) = pack2(v0, v1);
                    }
                }
            }
        }
    }
    #undef ISSUE
}

// =================== balanced fp16 causal flash attention (paired k-tiles) ===================
// Grid (NQT/2, HEADS, 2); CTA bx does q-tiles {NQT-1-bx, bx}. 2 CTAs/SM.
// Q pre-scaled by 0.125*log2e; V pre-scaled by 2^-4 -> p = exp2(s) raw.
// K-tiles processed in PAIRS per sync: smem Q 16KB + 2 pair-buffers x 32KB = 80KB.
#define ATTN_SMEM 81920

__global__ void __launch_bounds__(256, 2) attn_mma(
    const __half* __restrict__ qkv16, __half* __restrict__ ctx16)
{
    extern __shared__ char smem[];
    const uint32_t sb = smem_u32(smem);
    const int tid = threadIdx.x;
    const int w = tid >> 5, l = tid & 31;
    const int bx = blockIdx.x;
    const int h = blockIdx.y, b = blockIdx.z;
    const int btok = b * SEQL;
    const int wq0 = w * 16;
    const char* qkvb = (const char*)qkv16;
    const int qoff = 128 * h;
    const int koff = 2048 + 128 * h;
    const int voff = 4096 + 128 * h;

    #define PAIRLOAD(p) do { \
        uint32_t _pb = sb + 16384 + (uint32_t)((p) & 1) * 32768; \
        _Pragma("unroll") \
        for (int i = 0; i < 8; i++) { \
            int idx = tid + i * 256; \
            int t_ = idx >> 10; \
            int rem = idx & 1023; \
            int mat = rem >> 9; \
            int row = (rem >> 3) & 63; \
            int cc = rem & 7; \
            const char* _src = qkvb + (size_t)(btok + ((p) * 2 + t_) * 64 + row) * 6144 \
                + (mat ? voff : koff) + cc * 16; \
            CP_ASYNC16(_pb + t_ * 16384 + mat * 8192 + row * 128 + ((cc ^ (row & 7)) << 4), _src); \
        } \
    } while (0)

    #pragma unroll 1
    for (int pass = 0; pass < 2; pass++) {
        const int qt = pass ? bx : (NQT - 1 - bx);   // heavy first
        const int qbase = qt * 128;
        const int npairs = qt + 1;

        #pragma unroll
        for (int i = 0; i < 4; i++) {
            int idx = tid + i * 256;
            int row = idx >> 3, cc = idx & 7;
            const char* src = qkvb + (size_t)(btok + qbase + row) * 6144 + qoff + cc * 16;
            CP_ASYNC16(sb + row * 128 + ((cc ^ (row & 7)) << 4), src);
        }
        PAIRLOAD(0);
        CP_COMMIT();
        if (1 < npairs) PAIRLOAD(1);
        CP_COMMIT();

        CP_WAIT(1);
        __syncthreads();

        uint32_t qh[4][4];
        #pragma unroll
        for (int c = 0; c < 4; c++) {
            int cch = 2 * c + (l >> 4);
            int row = wq0 + (l & 15);
            LDSM4(qh[c], sb + row * 128 + ((cch ^ (row & 7)) << 4));
        }

        float o[8][4];
        #pragma unroll
        for (int nt = 0; nt < 8; nt++)
            #pragma unroll
            for (int j = 0; j < 4; j++) o[nt][j] = 0.f;
        float l0 = 0.f, l1 = 0.f;
        const int qrow0 = qbase + wq0 + (l >> 2);

        for (int p = 0; p < npairs; p++) {
            if (p) { CP_WAIT(1); __syncthreads(); }
            const uint32_t pb = sb + 16384 + (uint32_t)(p & 1) * 32768;

            #pragma unroll
            for (int tt = 0; tt < 2; tt++) {
                const int kt = 2 * p + tt;
                const int kbase = kt * 64;
                if (kbase > qbase + wq0 + 15) break;
                const uint32_t sK = pb + tt * 16384;
                const uint32_t sV = sK + 8192;

                float s4[8][4];
                #pragma unroll
                for (int nt = 0; nt < 8; nt++)
                    #pragma unroll
                    for (int j = 0; j < 4; j++) s4[nt][j] = 0.f;
                #pragma unroll
                for (int c = 0; c < 4; c++) {
                    int ch = 2 * c + ((l >> 3) & 1);
                    int rk = ((l >> 4) & 1) * 8 + (l & 7);
                    #pragma unroll
                    for (int nt2 = 0; nt2 < 4; nt2++) {
                        int r = nt2 * 16 + rk;
                        uint32_t bh[4];
                        LDSM4(bh, sK + r * 128 + ((ch ^ (r & 7)) << 4));
                        MMA16816(s4[2 * nt2],     qh[c], bh);
                        MMA16816(s4[2 * nt2 + 1], qh[c], bh + 2);
                    }
                }

                if (kbase + 63 > qbase + wq0) {
                    int col0 = kbase + 2 * (l & 3);
                    #pragma unroll
                    for (int nt = 0; nt < 8; nt++)
                        #pragma unroll
                        for (int j = 0; j < 4; j++) {
                            int col = col0 + nt * 8 + (j & 1);
                            int row = (j < 2) ? qrow0 : qrow0 + 8;
                            if (col > row) s4[nt][j] = -1e30f;
                        }
                }

                uint32_t pp[8][2];
                #pragma unroll
                for (int nt = 0; nt < 8; nt++) {
                    pp[nt][0] = exp2pack(s4[nt][0], s4[nt][1], l0);
                    pp[nt][1] = exp2pack(s4[nt][2], s4[nt][3], l1);
                }

                #pragma unroll
                for (int kc = 0; kc < 4; kc++) {
                    uint32_t aH[4];
                    aH[0] = pp[2 * kc][0];
                    aH[1] = pp[2 * kc][1];
                    aH[2] = pp[2 * kc + 1][0];
                    aH[3] = pp[2 * kc + 1][1];
                    int vrow = kc * 16 + ((l >> 3) & 1) * 8 + (l & 7);
                    #pragma unroll
                    for (int nt2 = 0; nt2 < 4; nt2++) {
                        int n = 2 * nt2 + (l >> 4);
                        uint32_t vh[4];
                        LDSM4T(vh, sV + vrow * 128 + ((n ^ (vrow & 7)) << 4));
                        MMA16816(o[2 * nt2],     aH, vh);
                        MMA16816(o[2 * nt2 + 1], aH, vh + 2);
                    }
                }
            }
            __syncthreads();
            if (p + 2 < npairs) PAIRLOAD(p + 2);
            CP_COMMIT();
        }

        #pragma unroll
        for (int msk = 1; msk < 4; msk <<= 1) {
            l0 += __shfl_xor_sync(0xffffffffu, l0, msk);
            l1 += __shfl_xor_sync(0xffffffffu, l1, msk);
        }
        float inv0 = INV_V_SCALE / l0, inv1 = INV_V_SCALE / l1;
        #pragma unroll
        for (int nt = 0; nt < 8; nt++) {
            int dh0 = nt * 8 + 2 * (l & 3);
            size_t base0 = (size_t)(btok + qrow0) * DM + h * 64 + dh0;
            *(uint32_t*)(ctx16 + base0) = pack2(o[nt][0] * inv0, o[nt][1] * inv0);
            size_t base1 = (size_t)(btok + qrow0 + 8) * DM + h * 64 + dh0;
            *(uint32_t*)(ctx16 + base1) = pack2(o[nt][2] * inv1, o[nt][3] * inv1);
        }
    }
    #undef PAIRLOAD
}

// ---------------- launch ----------------
extern "C" void kernel_launch(void* const* d_in, const int* in_sizes, int n_in,
                              void* d_out, int out_size)
{
    const float* x     = (const float*)d_in[0];
    const float* w_qkv = (const float*)d_in[1];
    const float* w_o   = (const float*)d_in[2];
    const float* ln1   = (const float*)d_in[3];
    const float* ln2   = (const float*)d_in[4];
    const float* w1    = (const float*)d_in[5];
    const float* w2    = (const float*)d_in[6];
    float* out = (float*)d_out;

    __half *h16, *qkv16, *ctx16, *ff116, *wqkvh, *woh, *w1h, *w2h;
    float *first;
    cudaGetSymbolAddress((void**)&h16, g_h16);
    cudaGetSymbolAddress((void**)&qkv16, g_qkv16);
    cudaGetSymbolAddress((void**)&ctx16, g_ctx16);
    cudaGetSymbolAddress((void**)&first, g_first);
    cudaGetSymbolAddress((void**)&ff116, g_ff116);
    cudaGetSymbolAddress((void**)&wqkvh, g_wqkvh);
    cudaGetSymbolAddress((void**)&woh, g_woh);
    cudaGetSymbolAddress((void**)&w1h, g_w1h);
    cudaGetSymbolAddress((void**)&w2h, g_w2h);

    cudaFuncSetAttribute(attn_mma, cudaFuncAttributeMaxDynamicSharedMemorySize, ATTN_SMEM);
    cudaFuncSetAttribute((gemm_mma<3, 3072, 1024>), cudaFuncAttributeMaxDynamicSharedMemorySize, GEMM_SMEM);
    cudaFuncSetAttribute((gemm_mma<2, 1024, 1024>), cudaFuncAttributeMaxDynamicSharedMemorySize, GEMM_SMEM);
    cudaFuncSetAttribute((gemm_mma<1, 4096, 1024>), cudaFuncAttributeMaxDynamicSharedMemorySize, GEMM_SMEM);
    cudaFuncSetAttribute((gemm_mma<2, 1024, 4096>), cudaFuncAttributeMaxDynamicSharedMemorySize, GEMM_SMEM);

    // fused weight conversion (4 float4 / thread)
    convert_all<<<3072, 256>>>((const float4*)w_qkv, (const float4*)w_o,
                               (const float4*)w1, (const float4*)w2,
                               wqkvh, woh, w1h, w2h);

    // 1. h = rmsnorm(x, ln1) -> fp16  (2 rows per block)
    rmsnorm_cv<<<NTOK / 2, 256>>>(x, ln1, h16);
    // 2. qkv16 = fp16(h @ w_qkv^T), Q*0.125log2e, V*2^-4  (4096 x 3072 x 1024)
    gemm_mma<3, 3072, 1024><<<GEMM_GRID, 256, GEMM_SMEM>>>(h16, wqkvh, nullptr, nullptr, qkv16);
    // 3. ctx16 = causal_attention(qkv16)  — balanced pairs, paired k-tiles, 2 CTAs/SM
    attn_mma<<<dim3(NQT / 2, HEADS, 2), 256, ATTN_SMEM>>>(qkv16, ctx16);
    // 4. first = x + ctx @ w_o^T
    gemm_mma<2, 1024, 1024><<<GEMM_GRID, 256, GEMM_SMEM>>>(ctx16, woh, x, first, nullptr);
    // 5. h = rmsnorm(first, ln2) -> fp16
    rmsnorm_cv<<<NTOK / 2, 256>>>(first, ln2, h16);
    // 6. ff116 = fp16(gelu(h @ w1^T))
    gemm_mma<1, 4096, 1024><<<GEMM_GRID, 256, GEMM_SMEM>>>(h16, w1h, nullptr, nullptr, ff116);
    // 7. out = first + ff1 @ w2^T
    gemm_mma<2, 1024, 4096><<<GEMM_GRID, 256, GEMM_SMEM>>>(ff116, w2h, first, out, nullptr);
}

// round 16
// speedup vs baseline: 1.0935x; 1.0060x over previous
#include <cuda_runtime.h>
#include <cuda_fp16.h>
#include <math.h>
#include <stdint.h>

#define NTOK 4096        // BATCH*SEQ
#define DM   1024
#define DFF  4096
#define SEQL 2048
#define HEADS 16
#define NQT  16          // SEQL / 128 q-tiles

// ---------------- scratch (no allocations allowed) ----------------
__device__ __half g_h16   [NTOK * DM];
__device__ __half g_qkv16 [NTOK * 3 * DM];
__device__ __half g_ctx16 [NTOK * DM];
__device__ float  g_first [NTOK * DM];
__device__ __half g_ff116 [NTOK * DFF];
__device__ __half g_wqkvh [3 * DM * DM];
__device__ __half g_woh   [DM * DM];
__device__ __half g_w1h   [DFF * DM];
__device__ __half g_w2h   [DM * DFF];

// =================== helpers ===================
__device__ __forceinline__ uint32_t smem_u32(const void* p) {
    uint32_t a;
    asm("{ .reg .u64 t; cvta.to.shared.u64 t, %1; cvt.u32.u64 %0, t; }" : "=r"(a) : "l"(p));
    return a;
}
#define CP_ASYNC16(dst, src) asm volatile("cp.async.cg.shared.global [%0], [%1], 16;" :: "r"(dst), "l"(src))
#define CP_COMMIT() asm volatile("cp.async.commit_group;" ::: "memory")
#define CP_WAIT(n)  asm volatile("cp.async.wait_group %0;" :: "n"(n) : "memory")

#define LDSM4(r, a) asm volatile("ldmatrix.sync.aligned.m8n8.x4.shared.b16 {%0,%1,%2,%3}, [%4];" \
    : "=r"((r)[0]), "=r"((r)[1]), "=r"((r)[2]), "=r"((r)[3]) : "r"(a))
#define LDSM4T(r, a) asm volatile("ldmatrix.sync.aligned.m8n8.x4.trans.shared.b16 {%0,%1,%2,%3}, [%4];" \
    : "=r"((r)[0]), "=r"((r)[1]), "=r"((r)[2]), "=r"((r)[3]) : "r"(a))

#define MMA16816(d, a, b) asm volatile( \
    "mma.sync.aligned.m16n8k16.row.col.f32.f16.f16.f32 " \
    "{%0,%1,%2,%3},{%4,%5,%6,%7},{%8,%9},{%0,%1,%2,%3};" \
    : "+f"((d)[0]), "+f"((d)[1]), "+f"((d)[2]), "+f"((d)[3]) \
    : "r"((a)[0]), "r"((a)[1]), "r"((a)[2]), "r"((a)[3]), "r"((b)[0]), "r"((b)[1]))

// single-instruction fp32x2 -> fp16x2 pack (lo = a, hi = b)
__device__ __forceinline__ uint32_t pack2(float a, float b) {
    uint32_t r;
    asm("cvt.rn.f16x2.f32 %0, %1, %2;" : "=r"(r) : "f"(b), "f"(a));
    return r;
}
// p = exp2fp16(pack(a,b)); accumulates fp32 sum of the two fp16 results
__device__ __forceinline__ uint32_t exp2pack(float a, float b, float& sum) {
    uint32_t s = pack2(a, b);
    __half2 p = h2exp2(*(__half2*)&s);
    float2 f = __half22float2(p);
    sum += f.x + f.y;
    return *(uint32_t*)&p;
}
__device__ __forceinline__ float gelu_erf(float x) {
    return 0.5f * x * (1.0f + erff(x * 0.70710678118654752f));
}

#define SCALE_LOG2E 0.1803368801111601f   // 0.125 * log2(e)
#define V_SCALE 0.0625f                   // 2^-4: shift folded into V
#define INV_V_SCALE 16.0f

// ---------------- fused prologue: weight convert (blocks 0..3071) + rmsnorm1 (3072..5119) ----------------
__global__ void __launch_bounds__(256) prologue(
    const float4* __restrict__ wqkv, const float4* __restrict__ wo,
    const float4* __restrict__ w1,   const float4* __restrict__ w2,
    __half* __restrict__ dq, __half* __restrict__ do_,
    __half* __restrict__ d1, __half* __restrict__ d2,
    const float* __restrict__ x, const float* __restrict__ ln1, __half* __restrict__ hout)
{
    if (blockIdx.x < 3072) {
        // ---- weight convert: 4 float4 per thread ----
        size_t i0 = ((size_t)blockIdx.x * 256 + threadIdx.x) * 4;
        const float4* src;
        __half* dst;
        size_t off;
        if (i0 < 786432)       { src = wqkv; dst = dq;  off = i0; }
        else if (i0 < 1048576) { src = wo;   dst = do_; off = i0 - 786432; }
        else if (i0 < 2097152) { src = w1;   dst = d1;  off = i0 - 1048576; }
        else                   { src = w2;   dst = d2;  off = i0 - 2097152; }
        float4 v0 = src[off], v1 = src[off + 1], v2 = src[off + 2], v3 = src[off + 3];
        uint4 o0 = make_uint4(pack2(v0.x, v0.y), pack2(v0.z, v0.w),
                              pack2(v1.x, v1.y), pack2(v1.z, v1.w));
        uint4 o1 = make_uint4(pack2(v2.x, v2.y), pack2(v2.z, v2.w),
                              pack2(v3.x, v3.y), pack2(v3.z, v3.w));
        *(uint4*)(dst + off * 4)     = o0;
        *(uint4*)(dst + off * 4 + 8) = o1;
    } else {
        // ---- rmsnorm1: 2 rows per block ----
        int row0 = (blockIdx.x - 3072) * 2;
        int t = threadIdx.x;
        float4 va = ((const float4*)(x + (size_t)row0 * DM))[t];
        float4 vb = ((const float4*)(x + (size_t)(row0 + 1) * DM))[t];
        float4 wv = ((const float4*)ln1)[t];
        float sa = va.x * va.x + va.y * va.y + va.z * va.z + va.w * va.w;
        float sq = vb.x * vb.x + vb.y * vb.y + vb.z * vb.z + vb.w * vb.w;
        #pragma unroll
        for (int m = 16; m > 0; m >>= 1) {
            sa += __shfl_xor_sync(0xffffffffu, sa, m);
            sq += __shfl_xor_sync(0xffffffffu, sq, m);
        }
        __shared__ float red[2][8];
        __shared__ float s_inv[2];
        if ((t & 31) == 0) { red[0][t >> 5] = sa; red[1][t >> 5] = sq; }
        __syncthreads();
        if (t < 2) {
            float tot = 0.f;
            #pragma unroll
            for (int i = 0; i < 8; i++) tot += red[t][i];
            s_inv[t] = 1.0f / sqrtf(tot / (float)DM + 1e-5f);
        }
        __syncthreads();
        float ia = s_inv[0], ib = s_inv[1];
        va.x *= ia * wv.x; va.y *= ia * wv.y; va.z *= ia * wv.z; va.w *= ia * wv.w;
        vb.x *= ib * wv.x; vb.y *= ib * wv.y; vb.z *= ib * wv.z; vb.w *= ib * wv.w;
        *(uint2*)(hout + (size_t)row0 * DM + t * 4) = make_uint2(pack2(va.x, va.y), pack2(va.z, va.w));
        *(uint2*)(hout + (size_t)(row0 + 1) * DM + t * 4) = make_uint2(pack2(vb.x, vb.y), pack2(vb.z, vb.w));
    }
}

// ---------------- RMSNorm -> fp16, 2 rows per block (row ILP) ----------------
__global__ void __launch_bounds__(256) rmsnorm_cv(
    const float* __restrict__ x, const float* __restrict__ w, __half* __restrict__ out)
{
    int row0 = blockIdx.x * 2;
    int t = threadIdx.x;
    float4 va = ((const float4*)(x + (size_t)row0 * DM))[t];
    float4 vb = ((const float4*)(x + (size_t)(row0 + 1) * DM))[t];
    float4 wv = ((const float4*)w)[t];
    float sa = va.x * va.x + va.y * va.y + va.z * va.z + va.w * va.w;
    float sq = vb.x * vb.x + vb.y * vb.y + vb.z * vb.z + vb.w * vb.w;
    #pragma unroll
    for (int m = 16; m > 0; m >>= 1) {
        sa += __shfl_xor_sync(0xffffffffu, sa, m);
        sq += __shfl_xor_sync(0xffffffffu, sq, m);
    }
    __shared__ float red[2][8];
    __shared__ float s_inv[2];
    if ((t & 31) == 0) { red[0][t >> 5] = sa; red[1][t >> 5] = sq; }
    __syncthreads();
    if (t < 2) {
        float tot = 0.f;
        #pragma unroll
        for (int i = 0; i < 8; i++) tot += red[t][i];
        s_inv[t] = 1.0f / sqrtf(tot / (float)DM + 1e-5f);
    }
    __syncthreads();
    float ia = s_inv[0], ib = s_inv[1];
    va.x *= ia * wv.x; va.y *= ia * wv.y; va.z *= ia * wv.z; va.w *= ia * wv.w;
    vb.x *= ib * wv.x; vb.y *= ib * wv.y; vb.z *= ib * wv.z; vb.w *= ib * wv.w;
    *(uint2*)(out + (size_t)row0 * DM + t * 4) = make_uint2(pack2(va.x, va.y), pack2(va.z, va.w));
    *(uint2*)(out + (size_t)(row0 + 1) * DM + t * 4) = make_uint2(pack2(vb.x, vb.y), pack2(vb.z, vb.w));
}

// =================== persistent fp16 mma.sync GEMM, compile-time N/K ===================
// 128x128 tiles, K-chunk 64, 3 stages x 32KB, 2 CTAs/SM, persistent grid 296. M = NTOK.
// EPI: 0 = plain fp32, 1 = erf-GELU -> fp16, 2 = residual fp32,
//      3 = fp16 QKV epilogue: Q cols (<DM) * SCALE_LOG2E, V cols (>=2*DM) * 2^-4
#define GSTAGE 32768
#define GEMM_SMEM (3 * GSTAGE)
#define GEMM_GRID 296

template<int EPI, int N, int K>
__global__ void __launch_bounds__(256, 2) gemm_mma(
    const __half* __restrict__ A, const __half* __restrict__ B,
    const float* __restrict__ R, float* __restrict__ C, __half* __restrict__ Ccv)
{
    extern __shared__ char smem[];
    const uint32_t sb = smem_u32(smem);
    const int tid = threadIdx.x;
    const int w = tid >> 5, l = tid & 31;
    const int warp_m = w & 1, warp_n = w >> 1;
    constexpr int nbn = N >> 7;
    constexpr int ntiles = (NTOK >> 7) * nbn;
    constexpr size_t rowB = (size_t)K * 2;
    constexpr int nc = K >> 6;
    constexpr size_t rstep = rowB << 5;
    const int stride = gridDim.x;

    const int rr = tid >> 3, cc = tid & 7;
    const uint32_t dA = sb + rr * 128 + ((cc ^ (rr & 7)) << 4);

    int tload = blockIdx.x;
    int cload = 0;
    int sload = 0;
    const char *pA = nullptr, *pB = nullptr;
    if (tload < ntiles) {
        int bm = (tload / nbn) << 7, bn = (tload % nbn) << 7;
        pA = (const char*)A + (size_t)(bm + rr) * rowB + cc * 16;
        pB = (const char*)B + (size_t)(bn + rr) * rowB + cc * 16;
    }

    #define ISSUE() do { \
        if (tload < ntiles) { \
            uint32_t _soff = (uint32_t)sload * GSTAGE; \
            size_t _g = (size_t)cload * 128; \
            _Pragma("unroll") \
            for (int i = 0; i < 4; i++) { \
                CP_ASYNC16(dA + _soff + i * 4096,         pA + _g + i * rstep); \
                CP_ASYNC16(dA + _soff + 16384 + i * 4096, pB + _g + i * rstep); \
            } \
            if (++cload == nc) { \
                cload = 0; tload += stride; \
                if (tload < ntiles) { \
                    int _bm = (tload / nbn) << 7, _bn = (tload % nbn) << 7; \
                    pA = (const char*)A + (size_t)(_bm + rr) * rowB + cc * 16; \
                    pB = (const char*)B + (size_t)(_bn + rr) * rowB + cc * 16; \
                } \
            } \
        } \
        sload = (sload + 1 == 3) ? 0 : sload + 1; \
        CP_COMMIT(); \
    } while (0)

    ISSUE();
    ISSUE();

    const int ra = warp_m * 64 + (l & 15);
    const int ca_half = (l >> 4);
    const int rb = warp_n * 32 + ((l >> 4) & 1) * 8 + (l & 7);
    const int cb_half = (l >> 3) & 1;

    int scons = 0;
    for (int t = blockIdx.x; t < ntiles; t += stride) {
        const int bm = (t / nbn) << 7, bn = (t % nbn) << 7;

        float d[4][4][4];
        #pragma unroll
        for (int mt = 0; mt < 4; mt++)
            #pragma unroll
            for (int nt = 0; nt < 4; nt++)
                #pragma unroll
                for (int j = 0; j < 4; j++) d[mt][nt][j] = 0.f;

        for (int c = 0; c < nc; c++) {
            CP_WAIT(1);
            __syncthreads();
            ISSUE();

            const uint32_t sA = sb + (uint32_t)scons * GSTAGE;
            const uint32_t sB = sA + 16384;

            #pragma unroll
            for (int ks = 0; ks < 4; ks++) {
                uint32_t ah[4][4], bh[2][4];
                #pragma unroll
                for (int mt = 0; mt < 4; mt++) {
                    int r = ra + mt * 16;
                    int ch = 2 * ks + ca_half;
                    LDSM4(ah[mt], sA + r * 128 + (((ch ^ (r & 7))) << 4));
                }
                #pragma unroll
                for (int p = 0; p < 2; p++) {
                    int r = rb + p * 16;
                    int ch = 2 * ks + cb_half;
                    LDSM4(bh[p], sB + r * 128 + (((ch ^ (r & 7))) << 4));
                }
                #pragma unroll
                for (int mt = 0; mt < 4; mt++)
                    #pragma unroll
                    for (int p = 0; p < 2; p++) {
                        MMA16816(d[mt][2 * p],     ah[mt], bh[p]);
                        MMA16816(d[mt][2 * p + 1], ah[mt], bh[p] + 2);
                    }
            }
            scons = (scons + 1 == 3) ? 0 : scons + 1;
        }

        const int gid = l >> 2, tid2 = l & 3;
        #pragma unroll
        for (int mt = 0; mt < 4; mt++) {
            #pragma unroll
            for (int nt = 0; nt < 4; nt++) {
                int col = bn + warp_n * 32 + nt * 8 + tid2 * 2;
                #pragma unroll
                for (int half = 0; half < 2; half++) {
                    int row = bm + warp_m * 64 + mt * 16 + gid + half * 8;
                    float v0 = d[mt][nt][half * 2], v1 = d[mt][nt][half * 2 + 1];
                    if (EPI == 0) {
                        *(float2*)&C[(size_t)row * N + col] = make_float2(v0, v1);
                    } else if (EPI == 2) {
                        float2 r2 = *(const float2*)&R[(size_t)row * N + col];
                        *(float2*)&C[(size_t)row * N + col] = make_float2(v0 + r2.x, v1 + r2.y);
                    } else {
                        if (EPI == 1) { v0 = gelu_erf(v0); v1 = gelu_erf(v1); }
                        if (EPI == 3) {
                            if (col < DM)          { v0 *= SCALE_LOG2E; v1 *= SCALE_LOG2E; }
                            else if (col >= 2 * DM){ v0 *= V_SCALE;     v1 *= V_SCALE; }
                        }
                        *(uint32_t*)(Ccv + (size_t)row * N + col) = pack2(v0, v1);
                    }
                }
            }
        }
    }
    #undef ISSUE
}

// =================== balanced fp16 causal flash attention (paired k-tiles) ===================
// Grid (NQT/2, HEADS, 2); CTA bx does q-tiles {NQT-1-bx, bx}. 2 CTAs/SM.
// Q pre-scaled by 0.125*log2e; V pre-scaled by 2^-4 -> p = exp2(s) raw.
// K-tiles processed in PAIRS per sync: smem Q 16KB + 2 pair-buffers x 32KB = 80KB.
// Split sum accumulators (a/b) shorten the FADD chain behind the MUFU exp2s.
#define ATTN_SMEM 81920

__global__ void __launch_bounds__(256, 2) attn_mma(
    const __half* __restrict__ qkv16, __half* __restrict__ ctx16)
{
    extern __shared__ char smem[];
    const uint32_t sb = smem_u32(smem);
    const int tid = threadIdx.x;
    const int w = tid >> 5, l = tid & 31;
    const int bx = blockIdx.x;
    const int h = blockIdx.y, b = blockIdx.z;
    const int btok = b * SEQL;
    const int wq0 = w * 16;
    const char* qkvb = (const char*)qkv16;
    const int qoff = 128 * h;
    const int koff = 2048 + 128 * h;
    const int voff = 4096 + 128 * h;

    #define PAIRLOAD(p) do { \
        uint32_t _pb = sb + 16384 + (uint32_t)((p) & 1) * 32768; \
        _Pragma("unroll") \
        for (int i = 0; i < 8; i++) { \
            int idx = tid + i * 256; \
            int t_ = idx >> 10; \
            int rem = idx & 1023; \
            int mat = rem >> 9; \
            int row = (rem >> 3) & 63; \
            int cc = rem & 7; \
            const char* _src = qkvb + (size_t)(btok + ((p) * 2 + t_) * 64 + row) * 6144 \
                + (mat ? voff : koff) + cc * 16; \
            CP_ASYNC16(_pb + t_ * 16384 + mat * 8192 + row * 128 + ((cc ^ (row & 7)) << 4), _src); \
        } \
    } while (0)

    #pragma unroll 1
    for (int pass = 0; pass < 2; pass++) {
        const int qt = pass ? bx : (NQT - 1 - bx);   // heavy first
        const int qbase = qt * 128;
        const int npairs = qt + 1;

        #pragma unroll
        for (int i = 0; i < 4; i++) {
            int idx = tid + i * 256;
            int row = idx >> 3, cc = idx & 7;
            const char* src = qkvb + (size_t)(btok + qbase + row) * 6144 + qoff + cc * 16;
            CP_ASYNC16(sb + row * 128 + ((cc ^ (row & 7)) << 4), src);
        }
        PAIRLOAD(0);
        CP_COMMIT();
        if (1 < npairs) PAIRLOAD(1);
        CP_COMMIT();

        CP_WAIT(1);
        __syncthreads();

        uint32_t qh[4][4];
        #pragma unroll
        for (int c = 0; c < 4; c++) {
            int cch = 2 * c + (l >> 4);
            int row = wq0 + (l & 15);
            LDSM4(qh[c], sb + row * 128 + ((cch ^ (row & 7)) << 4));
        }

        float o[8][4];
        #pragma unroll
        for (int nt = 0; nt < 8; nt++)
            #pragma unroll
            for (int j = 0; j < 4; j++) o[nt][j] = 0.f;
        float l0a = 0.f, l0b = 0.f, l1a = 0.f, l1b = 0.f;
        const int qrow0 = qbase + wq0 + (l >> 2);

        for (int p = 0; p < npairs; p++) {
            if (p) { CP_WAIT(1); __syncthreads(); }
            const uint32_t pb = sb + 16384 + (uint32_t)(p & 1) * 32768;

            #pragma unroll
            for (int tt = 0; tt < 2; tt++) {
                const int kt = 2 * p + tt;
                const int kbase = kt * 64;
                if (kbase > qbase + wq0 + 15) break;
                const uint32_t sK = pb + tt * 16384;
                const uint32_t sV = sK + 8192;

                float s4[8][4];
                #pragma unroll
                for (int nt = 0; nt < 8; nt++)
                    #pragma unroll
                    for (int j = 0; j < 4; j++) s4[nt][j] = 0.f;
                #pragma unroll
                for (int c = 0; c < 4; c++) {
                    int ch = 2 * c + ((l >> 3) & 1);
                    int rk = ((l >> 4) & 1) * 8 + (l & 7);
                    #pragma unroll
                    for (int nt2 = 0; nt2 < 4; nt2++) {
                        int r = nt2 * 16 + rk;
                        uint32_t bh[4];
                        LDSM4(bh, sK + r * 128 + ((ch ^ (r & 7)) << 4));
                        MMA16816(s4[2 * nt2],     qh[c], bh);
                        MMA16816(s4[2 * nt2 + 1], qh[c], bh + 2);
                    }
                }

                if (kbase + 63 > qbase + wq0) {
                    int col0 = kbase + 2 * (l & 3);
                    #pragma unroll
                    for (int nt = 0; nt < 8; nt++)
                        #pragma unroll
                        for (int j = 0; j < 4; j++) {
                            int col = col0 + nt * 8 + (j & 1);
                            int row = (j < 2) ? qrow0 : qrow0 + 8;
                            if (col > row) s4[nt][j] = -1e30f;
                        }
                }

                uint32_t pp[8][2];
                #pragma unroll
                for (int nt = 0; nt < 8; nt++) {
                    // even nt -> accumulator a, odd nt -> accumulator b (chain split)
                    if (nt & 1) {
                        pp[nt][0] = exp2pack(s4[nt][0], s4[nt][1], l0b);
                        pp[nt][1] = exp2pack(s4[nt][2], s4[nt][3], l1b);
                    } else {
                        pp[nt][0] = exp2pack(s4[nt][0], s4[nt][1], l0a);
                        pp[nt][1] = exp2pack(s4[nt][2], s4[nt][3], l1a);
                    }
                }

                #pragma unroll
                for (int kc = 0; kc < 4; kc++) {
                    uint32_t aH[4];
                    aH[0] = pp[2 * kc][0];
                    aH[1] = pp[2 * kc][1];
                    aH[2] = pp[2 * kc + 1][0];
                    aH[3] = pp[2 * kc + 1][1];
                    int vrow = kc * 16 + ((l >> 3) & 1) * 8 + (l & 7);
                    #pragma unroll
                    for (int nt2 = 0; nt2 < 4; nt2++) {
                        int n = 2 * nt2 + (l >> 4);
                        uint32_t vh[4];
                        LDSM4T(vh, sV + vrow * 128 + ((n ^ (vrow & 7)) << 4));
                        MMA16816(o[2 * nt2],     aH, vh);
                        MMA16816(o[2 * nt2 + 1], aH, vh + 2);
                    }
                }
            }
            __syncthreads();
            if (p + 2 < npairs) PAIRLOAD(p + 2);
            CP_COMMIT();
        }

        float l0 = l0a + l0b, l1 = l1a + l1b;
        #pragma unroll
        for (int msk = 1; msk < 4; msk <<= 1) {
            l0 += __shfl_xor_sync(0xffffffffu, l0, msk);
            l1 += __shfl_xor_sync(0xffffffffu, l1, msk);
        }
        float inv0 = INV_V_SCALE / l0, inv1 = INV_V_SCALE / l1;
        #pragma unroll
        for (int nt = 0; nt < 8; nt++) {
            int dh0 = nt * 8 + 2 * (l & 3);
            size_t base0 = (size_t)(btok + qrow0) * DM + h * 64 + dh0;
            *(uint32_t*)(ctx16 + base0) = pack2(o[nt][0] * inv0, o[nt][1] * inv0);
            size_t base1 = (size_t)(btok + qrow0 + 8) * DM + h * 64 + dh0;
            *(uint32_t*)(ctx16 + base1) = pack2(o[nt][2] * inv1, o[nt][3] * inv1);
        }
    }
    #undef PAIRLOAD
}

// ---------------- launch ----------------
extern "C" void kernel_launch(void* const* d_in, const int* in_sizes, int n_in,
                              void* d_out, int out_size)
{
    const float* x     = (const float*)d_in[0];
    const float* w_qkv = (const float*)d_in[1];
    const float* w_o   = (const float*)d_in[2];
    const float* ln1   = (const float*)d_in[3];
    const float* ln2   = (const float*)d_in[4];
    const float* w1    = (const float*)d_in[5];
    const float* w2    = (const float*)d_in[6];
    float* out = (float*)d_out;

    __half *h16, *qkv16, *ctx16, *ff116, *wqkvh, *woh, *w1h, *w2h;
    float *first;
    cudaGetSymbolAddress((void**)&h16, g_h16);
    cudaGetSymbolAddress((void**)&qkv16, g_qkv16);
    cudaGetSymbolAddress((void**)&ctx16, g_ctx16);
    cudaGetSymbolAddress((void**)&first, g_first);
    cudaGetSymbolAddress((void**)&ff116, g_ff116);
    cudaGetSymbolAddress((void**)&wqkvh, g_wqkvh);
    cudaGetSymbolAddress((void**)&woh, g_woh);
    cudaGetSymbolAddress((void**)&w1h, g_w1h);
    cudaGetSymbolAddress((void**)&w2h, g_w2h);

    cudaFuncSetAttribute(attn_mma, cudaFuncAttributeMaxDynamicSharedMemorySize, ATTN_SMEM);
    cudaFuncSetAttribute((gemm_mma<3, 3072, 1024>), cudaFuncAttributeMaxDynamicSharedMemorySize, GEMM_SMEM);
    cudaFuncSetAttribute((gemm_mma<2, 1024, 1024>), cudaFuncAttributeMaxDynamicSharedMemorySize, GEMM_SMEM);
    cudaFuncSetAttribute((gemm_mma<1, 4096, 1024>), cudaFuncAttributeMaxDynamicSharedMemorySize, GEMM_SMEM);
    cudaFuncSetAttribute((gemm_mma<2, 1024, 4096>), cudaFuncAttributeMaxDynamicSharedMemorySize, GEMM_SMEM);

    // 0+1. fused prologue: weight conversion || rmsnorm1 (concurrent)
    prologue<<<5120, 256>>>((const float4*)w_qkv, (const float4*)w_o,
                            (const float4*)w1, (const float4*)w2,
                            wqkvh, woh, w1h, w2h, x, ln1, h16);
    // 2. qkv16 = fp16(h @ w_qkv^T), Q*0.125log2e, V*2^-4  (4096 x 3072 x 1024)
    gemm_mma<3, 3072, 1024><<<GEMM_GRID, 256, GEMM_SMEM>>>(h16, wqkvh, nullptr, nullptr, qkv16);
    // 3. ctx16 = causal_attention(qkv16)  — balanced pairs, paired k-tiles, 2 CTAs/SM
    attn_mma<<<dim3(NQT / 2, HEADS, 2), 256, ATTN_SMEM>>>(qkv16, ctx16);
    // 4. first = x + ctx @ w_o^T
    gemm_mma<2, 1024, 1024><<<GEMM_GRID, 256, GEMM_SMEM>>>(ctx16, woh, x, first, nullptr);
    // 5. h = rmsnorm(first, ln2) -> fp16
    rmsnorm_cv<<<NTOK / 2, 256>>>(first, ln2, h16);
    // 6. ff116 = fp16(gelu(h @ w1^T))
    gemm_mma<1, 4096, 1024><<<GEMM_GRID, 256, GEMM_SMEM>>>(h16, w1h, nullptr, nullptr, ff116);
    // 7. out = first + ff1 @ w2^T
    gemm_mma<2, 1024, 4096><<<GEMM_GRID, 256, GEMM_SMEM>>>(ff116, w2h, first, out, nullptr);
}